// round 13
// baseline (speedup 1.0000x reference)
#include <cuda_runtime.h>
#include <cuda_bf16.h>
#include <cstdint>

// Problem dims (fixed)
#define B 64
#define S 2048
#define I 256
#define H 256
#define O 256
#define IH 512
#define G3 768
#define NROWS (B*S)

typedef unsigned long long ull;
typedef ulonglong2 u2;

#define FMA2(acc, a, b) asm("fma.rn.f32x2 %0, %1, %2, %0;" : "+l"(acc) : "l"(a), "l"(b))
#define DUP2(d, s)      asm("mov.b64 %0, {%1, %1};" : "=l"(d) : "f"(s))
#define UNPK2(lo, hi, a) asm("mov.b64 {%0, %1}, %2;" : "=f"(lo), "=f"(hi) : "l"(a))

// ---------------- scratch ----------------------------------------------------
__device__ float g_gx[(size_t)B * S * G3];
__device__ float g_hs[(size_t)B * S * H];
__device__ float g_Wx[G3 * I];
__device__ float g_bx[G3];
// L2 exchange state (per group): data single-buffered; per-storer flags
__device__ __align__(256) float    g_rhg[16][1024];        // [g][b*256+dim]
__device__ __align__(256) float    g_hg[16][1024];         // [g][b*256+dim]
__device__ __align__(256) unsigned g_frh[16][8][32];       // [g][src][storer] rh flags
__device__ __align__(256) unsigned g_fh [16][8][32];       // [g][src][storer] h flags

// ---------------- weight pack + exchange reset --------------------------------
__global__ void pack_weights(const float* __restrict__ Wr, const float* __restrict__ Wz,
                             const float* __restrict__ Wh, const float* __restrict__ br,
                             const float* __restrict__ bz, const float* __restrict__ bh)
{
    int m = blockIdx.x;
    int d = m & 255;
    const float* Wsrc = (m < 256) ? Wr : (m < 512 ? Wz : Wh);
    for (int k = threadIdx.x; k < I; k += blockDim.x)
        g_Wx[m * I + k] = Wsrc[(size_t)d * IH + k];
    if (threadIdx.x == 0)
        g_bx[m] = (m < 256 ? br : (m < 512 ? bz : bh))[d];
    // reset exchange state for this launch (h(-1)=0, all flags=0)
    if (m < 16) {
        for (int k = threadIdx.x; k < 1024; k += blockDim.x) g_hg[m][k] = 0.f;
        unsigned* fr = &g_frh[m][0][0];
        unsigned* fh = &g_fh[m][0][0];
        for (int k = threadIdx.x; k < 256; k += blockDim.x) { fr[k] = 0u; fh[k] = 0u; }
    }
}

// ---------------- tiled GEMM: C = A @ W^T + bias, K=256 ----------------------
__global__ void __launch_bounds__(256)
gemm_bias(const float* __restrict__ A, const float* __restrict__ W,
          const float* __restrict__ bias, float* __restrict__ C, int M)
{
    __shared__ float As[16][128];
    __shared__ float Bs[16][68];

    const int n0 = blockIdx.x * 128;
    const int m0 = blockIdx.y * 64;
    const int t  = threadIdx.x;
    const int tx = t & 15;
    const int ty = t >> 4;

    ull acc[4][4];
#pragma unroll
    for (int i = 0; i < 4; i++)
#pragma unroll
        for (int j = 0; j < 4; j++) acc[i][j] = 0ull;

    for (int k0 = 0; k0 < 256; k0 += 16) {
#pragma unroll
        for (int i = 0; i < 2; i++) {
            int idx = t + i * 256;
            int r = idx & 127, kg = idx >> 7;
            float4 v = *(const float4*)(A + (size_t)(n0 + r) * 256 + k0 + kg * 4);
            As[kg * 4 + 0][r] = v.x;
            As[kg * 4 + 1][r] = v.y;
            As[kg * 4 + 2][r] = v.z;
            As[kg * 4 + 3][r] = v.w;
        }
        {
            int r = t & 63, kg = t >> 6;
            float4 v = *(const float4*)(W + (size_t)(m0 + r) * 256 + k0 + kg * 4);
            Bs[kg * 4 + 0][r] = v.x;
            Bs[kg * 4 + 1][r] = v.y;
            Bs[kg * 4 + 2][r] = v.z;
            Bs[kg * 4 + 3][r] = v.w;
        }
        __syncthreads();
#pragma unroll
        for (int kk = 0; kk < 16; kk++) {
            const u2* ap = (const u2*)&As[kk][ty * 8];
            u2 aA = ap[0];
            u2 aB = ap[1];
            float4 bv = *(const float4*)&Bs[kk][tx * 4];
            ull b0, b1, b2, b3;
            DUP2(b0, bv.x); DUP2(b1, bv.y); DUP2(b2, bv.z); DUP2(b3, bv.w);
            FMA2(acc[0][0], aA.x, b0); FMA2(acc[0][1], aA.x, b1);
            FMA2(acc[0][2], aA.x, b2); FMA2(acc[0][3], aA.x, b3);
            FMA2(acc[1][0], aA.y, b0); FMA2(acc[1][1], aA.y, b1);
            FMA2(acc[1][2], aA.y, b2); FMA2(acc[1][3], aA.y, b3);
            FMA2(acc[2][0], aB.x, b0); FMA2(acc[2][1], aB.x, b1);
            FMA2(acc[2][2], aB.x, b2); FMA2(acc[2][3], aB.x, b3);
            FMA2(acc[3][0], aB.y, b0); FMA2(acc[3][1], aB.y, b1);
            FMA2(acc[3][2], aB.y, b2); FMA2(acc[3][3], aB.y, b3);
        }
        __syncthreads();
    }

    float b0 = bias[m0 + tx * 4 + 0];
    float b1 = bias[m0 + tx * 4 + 1];
    float b2 = bias[m0 + tx * 4 + 2];
    float b3 = bias[m0 + tx * 4 + 3];
#pragma unroll
    for (int ip = 0; ip < 4; ip++) {
        float l0, h0, l1, h1, l2, h2, l3, h3;
        UNPK2(l0, h0, acc[ip][0]); UNPK2(l1, h1, acc[ip][1]);
        UNPK2(l2, h2, acc[ip][2]); UNPK2(l3, h3, acc[ip][3]);
        int r = n0 + ty * 8 + ip * 2;
        float4 o0, o1;
        o0.x = l0 + b0; o0.y = l1 + b1; o0.z = l2 + b2; o0.w = l3 + b3;
        o1.x = h0 + b0; o1.y = h1 + b1; o1.z = h2 + b2; o1.w = h3 + b3;
        *(float4*)(C + (size_t)r * M + m0 + tx * 4)       = o0;
        *(float4*)(C + (size_t)(r + 1) * M + m0 + tx * 4) = o1;
    }
}

// profiler-slot alignment dummy
__global__ void dummy_k() {}

// ---------------- recurrent kernel -------------------------------------------
// R13 = R12 resubmitted (R12 bench died to container infra, not the kernel).
// L2 exchange with PER-THREAD release/acquire pairs + fused poll+stage.
// Producer storer: stg.cg one float4, then st.release.gpu its OWN flag word.
// Consumer lane: polls exactly the flag of the storer whose float4 it stages,
// stages immediately on detection (no bar/fence/RMW anywhere in the loop path;
// one group bar before compute).
#define RB 148             // floats per source-rank block in SMEM (4*36 + 4 pad)

__device__ __forceinline__ unsigned ld_acq(const unsigned* p)
{
    unsigned v;
    asm volatile("ld.acquire.gpu.global.u32 %0, [%1];" : "=r"(v) : "l"(p) : "memory");
    return v;
}
__device__ __forceinline__ void st_rel(unsigned* p, unsigned v)
{
    asm volatile("st.release.gpu.global.u32 [%0], %1;" :: "l"(p), "r"(v) : "memory");
}
__device__ __forceinline__ float4 ldg_cg4(const float* p)
{
    float4 v;
    asm volatile("ld.global.cg.v4.f32 {%0, %1, %2, %3}, [%4];"
                 : "=f"(v.x), "=f"(v.y), "=f"(v.z), "=f"(v.w) : "l"(p) : "memory");
    return v;
}
__device__ __forceinline__ void stg_cg4(float* p, float x, float y, float z, float w)
{
    asm volatile("st.global.cg.v4.f32 [%0], {%1, %2, %3, %4};"
                 :: "l"(p), "f"(x), "f"(y), "f"(z), "f"(w) : "memory");
}

extern "C" __global__ void __launch_bounds__(384, 1)
gru_rec(const float* __restrict__ gx, const float* __restrict__ Wr,
        const float* __restrict__ Wz, const float* __restrict__ Wh,
        float* __restrict__ hs, float* __restrict__ hlast)
{
    __shared__ __align__(16) float hbuf[8 * RB];     // staged h(s-1): [src rank][b][36]
    __shared__ __align__(16) float rhbuf[8 * RB];    // staged rh(s)
    volatile __shared__ float zbuf[128];             // [dd][batch]

    const int t  = threadIdx.x;
    const int cl = blockIdx.x >> 3;                  // group (batch quad)
    const int j  = blockIdx.x & 7;                   // rank within group (dim slice)
    const bool isA = (t < 256);

    const int e  = t & 7;
    const int qh = t & 3;
    const int dd = isA ? (t >> 3) : ((t >> 2) & 31);
    const int dimg = j * 32 + dd;

    float* grh = g_rhg[cl];
    float* ghg = g_hg[cl];

    // ---- weights into registers (identical to R10)
    ull w[32];
    if (isA) {
        const float* rr = Wr + (size_t)dimg * IH + 256 + e * 32;
        const float* rz = Wz + (size_t)dimg * IH + 256 + e * 32;
#pragma unroll
        for (int i = 0; i < 8; i++) {
            u2 v = *(const u2*)(rr + i * 4);
            w[2 * i] = v.x; w[2 * i + 1] = v.y;
            u2 u = *(const u2*)(rz + i * 4);
            w[16 + 2 * i] = u.x; w[17 + 2 * i] = u.y;
        }
    } else {
        const float* rw = Wh + (size_t)dimg * IH + 256 + qh * 64;
#pragma unroll
        for (int i = 0; i < 16; i++) {
            u2 v = *(const u2*)(rw + i * 4);
            w[2 * i] = v.x; w[2 * i + 1] = v.y;
        }
    }

    // ---- per-thread exchange pointers (hoisted out of the loop)
    const int lane = t & 31;
    const unsigned* pollH = nullptr;       // sub-A: flag this lane polls
    const float*    srcH  = nullptr;       // sub-A: f4 this lane stages
    float*          dstH  = nullptr;       // smem destination
    unsigned*       pubRH = nullptr;       // sub-A storer (lane<4): flag it publishes
    float*          datRH = nullptr;       // sub-A storer: f4 it stores
    const unsigned* pollRH0 = nullptr;     // sub-B: two flags (sources 2wb, 2wb+1)
    const unsigned* pollRH1 = nullptr;
    const float*    srcRH0  = nullptr;
    const float*    srcRH1  = nullptr;
    float*          dstRH0  = nullptr;
    float*          dstRH1  = nullptr;
    unsigned*       pubH    = nullptr;     // sub-B storer (lane<8): flag it publishes
    float*          datH    = nullptr;

    if (isA) {
        const int wid = t >> 5;                        // source this warp consumes
        const int wb = lane >> 3, half = (lane >> 2) & 1, b = lane & 3;
        pollH = &g_fh[cl][wid][lane];
        srcH  = ghg + b * 256 + wid * 32 + 8 * wb + 4 * half;
        dstH  = &hbuf[wid * RB + b * 36 + 8 * wb + 4 * half];
        if (lane < 4) {
            const int wa = t >> 5;                     // producer warp id (= dims 4wa..)
            const int pb = lane;                       // batch it stores
            pubRH = &g_frh[cl][j][wa * 4 + pb];
            datRH = grh + pb * 256 + j * 32 + 4 * wa;
        }
    } else {
        const int u = t - 256;
        const int wb = u >> 5;                         // warp 0..3 -> sources 2wb, 2wb+1
        const int wa = lane >> 2, b = lane & 3;        // rh storer decomposition
        pollRH0 = &g_frh[cl][2 * wb][lane];
        pollRH1 = &g_frh[cl][2 * wb + 1][lane];
        srcRH0  = grh + b * 256 + (2 * wb) * 32 + 4 * wa;
        srcRH1  = grh + b * 256 + (2 * wb + 1) * 32 + 4 * wa;
        dstRH0  = &rhbuf[(2 * wb) * RB + b * 36 + 4 * wa];
        dstRH1  = &rhbuf[(2 * wb + 1) * RB + b * 36 + 4 * wa];
        if (lane < 8) {
            const int half = (lane >> 2) & 1, pb = lane & 3;
            pubH = &g_fh[cl][j][wb * 8 + half * 4 + pb];
            datH = ghg + pb * 256 + j * 32 + 8 * wb + 4 * half;
        }
    }

    // ---- gx prefetch (depth 2), one float per thread per step
    const int mybatch = isA ? (e & 3) : qh;
    const int myoff   = isA ? (((e < 4) ? 0 : 256) + dimg) : (512 + dimg);
    const float* gptr = gx + ((size_t)(cl * 4 + mybatch) * S) * G3 + myoff;
    float gv0 = __ldg(gptr);
    float gv1 = __ldg(gptr + G3);

    for (int s = 0; s < S; s++) {
        float gv = gv0;
        gv0 = gv1;
        if (s + 2 < S) gv1 = __ldg(gptr + 2 * G3);
        gptr += G3;

        if (isA) {
            // ---- fused poll+stage of h(s-1): lane waits ONLY its storer's flag
            {
                const unsigned tgt = (unsigned)s;      // h(s-1) published with value s
                while (ld_acq(pollH) < tgt) { }
                float4 v = ldg_cg4(srcH);
                *(float4*)dstH = v;
            }
            asm volatile("bar.sync 1, 256;" ::: "memory");

            const float* hbp = hbuf + e * RB;
            // ---- r and z dots interleaved over one h stream (R10 body)
            ull r0 = 0ull, r1 = 0ull, r2 = 0ull, r3 = 0ull;
            ull z0 = 0ull, z1 = 0ull, z2 = 0ull, z3 = 0ull;
            {
                const u2* p0 = (const u2*)(hbp + 0 * 36);
                const u2* p1 = (const u2*)(hbp + 1 * 36);
                const u2* p2 = (const u2*)(hbp + 2 * 36);
                const u2* p3 = (const u2*)(hbp + 3 * 36);
#pragma unroll
                for (int i = 0; i < 8; i++) {
                    u2 x0 = p0[i], x1 = p1[i], x2 = p2[i], x3 = p3[i];
                    FMA2(r0, w[2 * i], x0.x); FMA2(r0, w[2 * i + 1], x0.y);
                    FMA2(z0, w[16 + 2 * i], x0.x); FMA2(z0, w[17 + 2 * i], x0.y);
                    FMA2(r1, w[2 * i], x1.x); FMA2(r1, w[2 * i + 1], x1.y);
                    FMA2(z1, w[16 + 2 * i], x1.x); FMA2(z1, w[17 + 2 * i], x1.y);
                    FMA2(r2, w[2 * i], x2.x); FMA2(r2, w[2 * i + 1], x2.y);
                    FMA2(z2, w[16 + 2 * i], x2.x); FMA2(z2, w[17 + 2 * i], x2.y);
                    FMA2(r3, w[2 * i], x3.x); FMA2(r3, w[2 * i + 1], x3.y);
                    FMA2(z3, w[16 + 2 * i], x3.x); FMA2(z3, w[17 + 2 * i], x3.y);
                }
            }
            float lo, hi;
            float pr0, pr1, pr2, pr3, pz0, pz1, pz2, pz3;
            UNPK2(lo, hi, r0); pr0 = lo + hi;
            UNPK2(lo, hi, z0); pz0 = lo + hi;
            UNPK2(lo, hi, r1); pr1 = lo + hi;
            UNPK2(lo, hi, z1); pz1 = lo + hi;
            UNPK2(lo, hi, r2); pr2 = lo + hi;
            UNPK2(lo, hi, z2); pz2 = lo + hi;
            UNPK2(lo, hi, r3); pr3 = lo + hi;
            UNPK2(lo, hi, z3); pz3 = lo + hi;
            pr0 += __shfl_xor_sync(0xffffffffu, pr0, 4);
            pz0 += __shfl_xor_sync(0xffffffffu, pz0, 4);
            pr1 += __shfl_xor_sync(0xffffffffu, pr1, 4);
            pz1 += __shfl_xor_sync(0xffffffffu, pz1, 4);
            pr2 += __shfl_xor_sync(0xffffffffu, pr2, 4);
            pz2 += __shfl_xor_sync(0xffffffffu, pz2, 4);
            pr3 += __shfl_xor_sync(0xffffffffu, pr3, 4);
            pz3 += __shfl_xor_sync(0xffffffffu, pz3, 4);
            const int qe = e & 3;
            float ur01 = (qe & 1) ? pr0 : pr1;
            float uz01 = (qe & 1) ? pz0 : pz1;
            ur01 = __shfl_xor_sync(0xffffffffu, ur01, 1);
            uz01 = __shfl_xor_sync(0xffffffffu, uz01, 1);
            float vr0 = ((qe & 1) ? pr1 : pr0) + ur01;
            float vz0 = ((qe & 1) ? pz1 : pz0) + uz01;
            float ur23 = (qe & 1) ? pr2 : pr3;
            float uz23 = (qe & 1) ? pz2 : pz3;
            ur23 = __shfl_xor_sync(0xffffffffu, ur23, 1);
            uz23 = __shfl_xor_sync(0xffffffffu, uz23, 1);
            float vr1 = ((qe & 1) ? pr3 : pr2) + ur23;
            float vz1 = ((qe & 1) ? pz3 : pz2) + uz23;
            float wr = (qe & 2) ? vr0 : vr1;
            float wz = (qe & 2) ? vz0 : vz1;
            wr = __shfl_xor_sync(0xffffffffu, wr, 2);
            wz = __shfl_xor_sync(0xffffffffu, wz, 2);
            float tot_r = ((qe & 2) ? vr1 : vr0) + wr;
            float tot_z = ((qe & 2) ? vz1 : vz0) + wz;

            // rh value on e<4 lanes; z to SMEM on e>=4 lanes
            float rh = 0.f;
            if (e < 4) {
                float gate = __fdividef(1.f, 1.f + __expf(-(tot_r + gv)));
                float hold = hbuf[j * RB + qe * 36 + dd];
                rh = gate * hold;
            } else {
                float gate = __fdividef(1.f, 1.f + __expf(-(tot_z + gv)));
                zbuf[dd * 4 + qe] = gate;
            }
            // order zbuf STS (e>=4 lanes) before storer's release (lane<4)
            __syncwarp();
            {
                const int b = lane & 3;
                float g0 = __shfl_sync(0xffffffffu, rh, b);
                float g1 = __shfl_sync(0xffffffffu, rh, 8 + b);
                float g2 = __shfl_sync(0xffffffffu, rh, 16 + b);
                float g3 = __shfl_sync(0xffffffffu, rh, 24 + b);
                if (lane < 4) {
                    stg_cg4(datRH, g0, g1, g2, g3);
                    st_rel(pubRH, (unsigned)(s + 1));
                }
            }
        } else {
            // ---- fused poll+stage of rh(s): each lane handles its two storers
            {
                const unsigned tgt = (unsigned)(s + 1);
                while (ld_acq(pollRH0) < tgt) { }
                float4 v0 = ldg_cg4(srcRH0);
                *(float4*)dstRH0 = v0;
                while (ld_acq(pollRH1) < tgt) { }
                float4 v1 = ldg_cg4(srcRH1);
                *(float4*)dstRH1 = v1;
            }
            asm volatile("bar.sync 2, 128;" ::: "memory");

            ull a0 = 0ull, a1 = 0ull, a2 = 0ull, a3 = 0ull;
            const float* rp0 = rhbuf + (2 * qh) * RB;
            const float* rp1 = rhbuf + (2 * qh + 1) * RB;
#define SUBB_BATCH(ACC, BIDX)                                                   \
            {                                                                   \
                const u2* pa = (const u2*)(rp0 + (BIDX) * 36);                  \
                const u2* pb = (const u2*)(rp1 + (BIDX) * 36);                  \
                _Pragma("unroll")                                               \
                for (int i = 0; i < 8; i++) {                                   \
                    u2 xa = pa[i];                                              \
                    FMA2(ACC, w[2 * i], xa.x); FMA2(ACC, w[2 * i + 1], xa.y);   \
                }                                                               \
                _Pragma("unroll")                                               \
                for (int i = 0; i < 8; i++) {                                   \
                    u2 xb = pb[i];                                              \
                    FMA2(ACC, w[16 + 2 * i], xb.x); FMA2(ACC, w[17 + 2 * i], xb.y); \
                }                                                               \
            }
            SUBB_BATCH(a0, 0)
            SUBB_BATCH(a1, 1)
            SUBB_BATCH(a2, 2)
            SUBB_BATCH(a3, 3)
#undef SUBB_BATCH

            float lo, hi, p0f, p1f, p2f, p3f;
            UNPK2(lo, hi, a0); p0f = lo + hi;
            UNPK2(lo, hi, a1); p1f = lo + hi;
            UNPK2(lo, hi, a2); p2f = lo + hi;
            UNPK2(lo, hi, a3); p3f = lo + hi;
            float u01 = (qh & 1) ? p0f : p1f;
            u01 = __shfl_xor_sync(0xffffffffu, u01, 1);
            float v0 = ((qh & 1) ? p1f : p0f) + u01;
            float u23 = (qh & 1) ? p2f : p3f;
            u23 = __shfl_xor_sync(0xffffffffu, u23, 1);
            float v1 = ((qh & 1) ? p3f : p2f) + u23;
            float uu = (qh & 2) ? v0 : v1;
            uu = __shfl_xor_sync(0xffffffffu, uu, 2);
            float tot = ((qh & 2) ? v1 : v0) + uu;

            float pre2 = tot + gv;
            float e2 = __expf(2.f * pre2);
            float htil = 1.f - __fdividef(2.f, e2 + 1.f);
            float hold = hbuf[j * RB + qh * 36 + dd];
            float z = zbuf[dd * 4 + qh];                  // volatile SMEM read
            float hn = fmaf(z, htil - hold, hold);

            // gather + publish h: storer lane stores f4 then releases ITS flag
            {
                const int b = lane & 3;
                const int half = (lane >> 2) & 1;
                const int base = half ? 16 : 0;
                float g0 = __shfl_sync(0xffffffffu, hn, base + b + 0);
                float g1 = __shfl_sync(0xffffffffu, hn, base + b + 4);
                float g2 = __shfl_sync(0xffffffffu, hn, base + b + 8);
                float g3 = __shfl_sync(0xffffffffu, hn, base + b + 12);
                if (lane < 8) {
                    stg_cg4(datH, g0, g1, g2, g3);
                    st_rel(pubH, (unsigned)(s + 1));
                }
            }
            hs[((size_t)(cl * 4 + qh) * S + s) * H + dimg] = hn;
            if (s == S - 1) hlast[(size_t)(cl * 4 + qh) * H + dimg] = hn;
        }
    }
}

// ---------------- launch ------------------------------------------------------
extern "C" void kernel_launch(void* const* d_in, const int* in_sizes, int n_in,
                              void* d_out, int out_size)
{
    const float* x    = (const float*)d_in[0];
    const float* W_r  = (const float*)d_in[1];
    const float* b_r  = (const float*)d_in[2];
    const float* W_z  = (const float*)d_in[3];
    const float* b_z  = (const float*)d_in[4];
    const float* W_h  = (const float*)d_in[5];
    const float* b_h  = (const float*)d_in[6];
    const float* W_fc = (const float*)d_in[7];
    const float* b_fc = (const float*)d_in[8];
    float* out = (float*)d_out;
    float* hlast = out + (size_t)B * S * O;

    float *gx, *hsp, *Wx, *bx;
    cudaGetSymbolAddress((void**)&gx,  g_gx);
    cudaGetSymbolAddress((void**)&hsp, g_hs);
    cudaGetSymbolAddress((void**)&Wx,  g_Wx);
    cudaGetSymbolAddress((void**)&bx,  g_bx);

    pack_weights<<<G3, 64>>>(W_r, W_z, W_h, b_r, b_z, b_h);   // also resets exchange state
    gemm_bias<<<dim3(NROWS / 128, G3 / 64), 256>>>(x, Wx, bx, gx, G3);
    dummy_k<<<1, 32>>>();   // keeps gru_rec on the ncu capture slot
    gru_rec<<<128, 384>>>(gx, W_r, W_z, W_h, hsp, hlast);
    gemm_bias<<<dim3(NROWS / 128, O / 64), 256>>>(hsp, W_fc, b_fc, out, O);
}

// round 15
// speedup vs baseline: 1.1580x; 1.1580x over previous
#include <cuda_runtime.h>
#include <cuda_bf16.h>
#include <cstdint>

// Problem dims (fixed)
#define B 64
#define S 2048
#define I 256
#define H 256
#define O 256
#define IH 512
#define G3 768
#define NROWS (B*S)

typedef unsigned long long ull;
typedef ulonglong2 u2;

#define FMA2(acc, a, b) asm("fma.rn.f32x2 %0, %1, %2, %0;" : "+l"(acc) : "l"(a), "l"(b))
#define DUP2(d, s)      asm("mov.b64 %0, {%1, %1};" : "=l"(d) : "f"(s))
#define UNPK2(lo, hi, a) asm("mov.b64 {%0, %1}, %2;" : "=f"(lo), "=f"(hi) : "l"(a))

// ---------------- scratch ----------------------------------------------------
__device__ float g_gx[(size_t)B * S * G3];
__device__ float g_hs[(size_t)B * S * H];
__device__ float g_Wx[G3 * I];
__device__ float g_bx[G3];
// L2 exchange state (per group): data single-buffered, flags monotonic per launch
__device__ __align__(256) float    g_rhg[16][1024];    // [g][b*256+dim]
__device__ __align__(256) float    g_hg[16][1024];     // [g][b*256+dim]
__device__ __align__(256) unsigned g_flags[16][64];    // [g][0]=rh counter, [g][32]=h counter

// ---------------- weight pack + exchange reset --------------------------------
__global__ void pack_weights(const float* __restrict__ Wr, const float* __restrict__ Wz,
                             const float* __restrict__ Wh, const float* __restrict__ br,
                             const float* __restrict__ bz, const float* __restrict__ bh)
{
    int m = blockIdx.x;
    int d = m & 255;
    const float* Wsrc = (m < 256) ? Wr : (m < 512 ? Wz : Wh);
    for (int k = threadIdx.x; k < I; k += blockDim.x)
        g_Wx[m * I + k] = Wsrc[(size_t)d * IH + k];
    if (threadIdx.x == 0)
        g_bx[m] = (m < 256 ? br : (m < 512 ? bz : bh))[d];
    // reset exchange state for this launch (h(-1)=0, counters=0)
    if (m < 16) {
        for (int k = threadIdx.x; k < 1024; k += blockDim.x) g_hg[m][k] = 0.f;
        if (threadIdx.x == 0) { g_flags[m][0] = 0u; g_flags[m][32] = 0u; }
    }
}

// ---------------- tiled GEMM: C = A @ W^T + bias, K=256 ----------------------
__global__ void __launch_bounds__(256, 4)
gemm_bias(const float* __restrict__ A, const float* __restrict__ W,
          const float* __restrict__ bias, float* __restrict__ C, int M)
{
    __shared__ float As[16][128];
    __shared__ float Bs[16][68];

    const int n0 = blockIdx.x * 128;
    const int m0 = blockIdx.y * 64;
    const int t  = threadIdx.x;
    const int tx = t & 15;
    const int ty = t >> 4;

    ull acc[4][4];
#pragma unroll
    for (int i = 0; i < 4; i++)
#pragma unroll
        for (int j = 0; j < 4; j++) acc[i][j] = 0ull;

    for (int k0 = 0; k0 < 256; k0 += 16) {
#pragma unroll
        for (int i = 0; i < 2; i++) {
            int idx = t + i * 256;
            int r = idx & 127, kg = idx >> 7;
            float4 v = *(const float4*)(A + (size_t)(n0 + r) * 256 + k0 + kg * 4);
            As[kg * 4 + 0][r] = v.x;
            As[kg * 4 + 1][r] = v.y;
            As[kg * 4 + 2][r] = v.z;
            As[kg * 4 + 3][r] = v.w;
        }
        {
            int r = t & 63, kg = t >> 6;
            float4 v = *(const float4*)(W + (size_t)(m0 + r) * 256 + k0 + kg * 4);
            Bs[kg * 4 + 0][r] = v.x;
            Bs[kg * 4 + 1][r] = v.y;
            Bs[kg * 4 + 2][r] = v.z;
            Bs[kg * 4 + 3][r] = v.w;
        }
        __syncthreads();
#pragma unroll
        for (int kk = 0; kk < 16; kk++) {
            const u2* ap = (const u2*)&As[kk][ty * 8];
            u2 aA = ap[0];
            u2 aB = ap[1];
            float4 bv = *(const float4*)&Bs[kk][tx * 4];
            ull b0, b1, b2, b3;
            DUP2(b0, bv.x); DUP2(b1, bv.y); DUP2(b2, bv.z); DUP2(b3, bv.w);
            FMA2(acc[0][0], aA.x, b0); FMA2(acc[0][1], aA.x, b1);
            FMA2(acc[0][2], aA.x, b2); FMA2(acc[0][3], aA.x, b3);
            FMA2(acc[1][0], aA.y, b0); FMA2(acc[1][1], aA.y, b1);
            FMA2(acc[1][2], aA.y, b2); FMA2(acc[1][3], aA.y, b3);
            FMA2(acc[2][0], aB.x, b0); FMA2(acc[2][1], aB.x, b1);
            FMA2(acc[2][2], aB.x, b2); FMA2(acc[2][3], aB.x, b3);
            FMA2(acc[3][0], aB.y, b0); FMA2(acc[3][1], aB.y, b1);
            FMA2(acc[3][2], aB.y, b2); FMA2(acc[3][3], aB.y, b3);
        }
        __syncthreads();
    }

    float b0 = bias[m0 + tx * 4 + 0];
    float b1 = bias[m0 + tx * 4 + 1];
    float b2 = bias[m0 + tx * 4 + 2];
    float b3 = bias[m0 + tx * 4 + 3];
#pragma unroll
    for (int ip = 0; ip < 4; ip++) {
        float l0, h0, l1, h1, l2, h2, l3, h3;
        UNPK2(l0, h0, acc[ip][0]); UNPK2(l1, h1, acc[ip][1]);
        UNPK2(l2, h2, acc[ip][2]); UNPK2(l3, h3, acc[ip][3]);
        int r = n0 + ty * 8 + ip * 2;
        float4 o0, o1;
        o0.x = l0 + b0; o0.y = l1 + b1; o0.z = l2 + b2; o0.w = l3 + b3;
        o1.x = h0 + b0; o1.y = h1 + b1; o1.z = h2 + b2; o1.w = h3 + b3;
        *(float4*)(C + (size_t)r * M + m0 + tx * 4)       = o0;
        *(float4*)(C + (size_t)(r + 1) * M + m0 + tx * 4) = o1;
    }
}

// profiler-slot alignment dummy
__global__ void dummy_k() {}

// ---------------- recurrent kernel -------------------------------------------
// R15 = R10 (proven best) with polling DECONTENDED: only warp 0 (sub-A) /
// warp 8 (sub-B) polls the flag; other warps park at the group bar.sync.
// Producers unchanged: per-storer stg.cg4 + red.release.gpu (NO fence).
#define RB 148             // floats per source-rank block in SMEM (4*36 + 4 pad)

__device__ __forceinline__ unsigned ld_acq(const unsigned* p)
{
    unsigned v;
    asm volatile("ld.acquire.gpu.global.u32 %0, [%1];" : "=r"(v) : "l"(p) : "memory");
    return v;
}
__device__ __forceinline__ void red_rel(unsigned* p)
{
    asm volatile("red.release.gpu.global.add.u32 [%0], 1;" :: "l"(p) : "memory");
}
__device__ __forceinline__ float4 ldg_cg4(const float* p)
{
    float4 v;
    asm volatile("ld.global.cg.v4.f32 {%0, %1, %2, %3}, [%4];"
                 : "=f"(v.x), "=f"(v.y), "=f"(v.z), "=f"(v.w) : "l"(p) : "memory");
    return v;
}
__device__ __forceinline__ void stg_cg4(float* p, float x, float y, float z, float w)
{
    asm volatile("st.global.cg.v4.f32 [%0], {%1, %2, %3, %4};"
                 :: "l"(p), "f"(x), "f"(y), "f"(z), "f"(w) : "memory");
}

extern "C" __global__ void __launch_bounds__(384, 1)
gru_rec(const float* __restrict__ gx, const float* __restrict__ Wr,
        const float* __restrict__ Wz, const float* __restrict__ Wh,
        float* __restrict__ hs, float* __restrict__ hlast)
{
    __shared__ __align__(16) float hbuf[8 * RB];     // staged h(s-1): [src rank][b][36]
    __shared__ __align__(16) float rhbuf[8 * RB];    // staged rh(s)
    volatile __shared__ float zbuf[128];             // [dd][batch]

    const int t  = threadIdx.x;
    const int cl = blockIdx.x >> 3;                  // group (batch quad)
    const int j  = blockIdx.x & 7;                   // rank within group (dim slice)
    const bool isA = (t < 256);

    const int e  = t & 7;
    const int qh = t & 3;
    const int dd = isA ? (t >> 3) : ((t >> 2) & 31);
    const int dimg = j * 32 + dd;

    float*    grh    = g_rhg[cl];
    float*    ghg    = g_hg[cl];
    unsigned* flagRH = &g_flags[cl][0];
    unsigned* flagH  = &g_flags[cl][32];

    // ---- weights into registers (identical to R10)
    ull w[32];
    if (isA) {
        const float* rr = Wr + (size_t)dimg * IH + 256 + e * 32;
        const float* rz = Wz + (size_t)dimg * IH + 256 + e * 32;
#pragma unroll
        for (int i = 0; i < 8; i++) {
            u2 v = *(const u2*)(rr + i * 4);
            w[2 * i] = v.x; w[2 * i + 1] = v.y;
            u2 u = *(const u2*)(rz + i * 4);
            w[16 + 2 * i] = u.x; w[17 + 2 * i] = u.y;
        }
    } else {
        const float* rw = Wh + (size_t)dimg * IH + 256 + qh * 64;
#pragma unroll
        for (int i = 0; i < 16; i++) {
            u2 v = *(const u2*)(rw + i * 4);
            w[2 * i] = v.x; w[2 * i + 1] = v.y;
        }
    }

    // ---- gx prefetch (depth 2), one float per thread per step
    const int mybatch = isA ? (e & 3) : qh;
    const int myoff   = isA ? (((e < 4) ? 0 : 256) + dimg) : (512 + dimg);
    const float* gptr = gx + ((size_t)(cl * 4 + mybatch) * S) * G3 + myoff;
    float gv0 = __ldg(gptr);
    float gv1 = __ldg(gptr + G3);

    for (int s = 0; s < S; s++) {
        float gv = gv0;
        gv0 = gv1;
        if (s + 2 < S) gv1 = __ldg(gptr + 2 * G3);
        gptr += G3;

        if (isA) {
            // ---- wait h(s-1): warp 0 polls; warps 1-7 park at the bar
            if ((t >> 5) == 0 && s > 0) {
                const unsigned tgt = 256u * (unsigned)s;
                while (ld_acq(flagH) < tgt) { }
            }
            asm volatile("bar.sync 1, 256;" ::: "memory");
            // ---- stage h(s-1) global -> smem (each thread one float4)
            {
                const int wid = t >> 5, b = (t >> 3) & 3, q = t & 7;
                float4 v = ldg_cg4(ghg + b * 256 + wid * 32 + q * 4);
                *(float4*)&hbuf[wid * RB + b * 36 + q * 4] = v;
            }
            asm volatile("bar.sync 1, 256;" ::: "memory");

            const float* hbp = hbuf + e * RB;
            // ---- r and z dots interleaved over one h stream (R10 body)
            ull r0 = 0ull, r1 = 0ull, r2 = 0ull, r3 = 0ull;
            ull z0 = 0ull, z1 = 0ull, z2 = 0ull, z3 = 0ull;
            {
                const u2* p0 = (const u2*)(hbp + 0 * 36);
                const u2* p1 = (const u2*)(hbp + 1 * 36);
                const u2* p2 = (const u2*)(hbp + 2 * 36);
                const u2* p3 = (const u2*)(hbp + 3 * 36);
#pragma unroll
                for (int i = 0; i < 8; i++) {
                    u2 x0 = p0[i], x1 = p1[i], x2 = p2[i], x3 = p3[i];
                    FMA2(r0, w[2 * i], x0.x); FMA2(r0, w[2 * i + 1], x0.y);
                    FMA2(z0, w[16 + 2 * i], x0.x); FMA2(z0, w[17 + 2 * i], x0.y);
                    FMA2(r1, w[2 * i], x1.x); FMA2(r1, w[2 * i + 1], x1.y);
                    FMA2(z1, w[16 + 2 * i], x1.x); FMA2(z1, w[17 + 2 * i], x1.y);
                    FMA2(r2, w[2 * i], x2.x); FMA2(r2, w[2 * i + 1], x2.y);
                    FMA2(z2, w[16 + 2 * i], x2.x); FMA2(z2, w[17 + 2 * i], x2.y);
                    FMA2(r3, w[2 * i], x3.x); FMA2(r3, w[2 * i + 1], x3.y);
                    FMA2(z3, w[16 + 2 * i], x3.x); FMA2(z3, w[17 + 2 * i], x3.y);
                }
            }
            float lo, hi;
            float pr0, pr1, pr2, pr3, pz0, pz1, pz2, pz3;
            UNPK2(lo, hi, r0); pr0 = lo + hi;
            UNPK2(lo, hi, z0); pz0 = lo + hi;
            UNPK2(lo, hi, r1); pr1 = lo + hi;
            UNPK2(lo, hi, z1); pz1 = lo + hi;
            UNPK2(lo, hi, r2); pr2 = lo + hi;
            UNPK2(lo, hi, z2); pz2 = lo + hi;
            UNPK2(lo, hi, r3); pr3 = lo + hi;
            UNPK2(lo, hi, z3); pz3 = lo + hi;
            pr0 += __shfl_xor_sync(0xffffffffu, pr0, 4);
            pz0 += __shfl_xor_sync(0xffffffffu, pz0, 4);
            pr1 += __shfl_xor_sync(0xffffffffu, pr1, 4);
            pz1 += __shfl_xor_sync(0xffffffffu, pz1, 4);
            pr2 += __shfl_xor_sync(0xffffffffu, pr2, 4);
            pz2 += __shfl_xor_sync(0xffffffffu, pz2, 4);
            pr3 += __shfl_xor_sync(0xffffffffu, pr3, 4);
            pz3 += __shfl_xor_sync(0xffffffffu, pz3, 4);
            const int qe = e & 3;
            float ur01 = (qe & 1) ? pr0 : pr1;
            float uz01 = (qe & 1) ? pz0 : pz1;
            ur01 = __shfl_xor_sync(0xffffffffu, ur01, 1);
            uz01 = __shfl_xor_sync(0xffffffffu, uz01, 1);
            float vr0 = ((qe & 1) ? pr1 : pr0) + ur01;
            float vz0 = ((qe & 1) ? pz1 : pz0) + uz01;
            float ur23 = (qe & 1) ? pr2 : pr3;
            float uz23 = (qe & 1) ? pz2 : pz3;
            ur23 = __shfl_xor_sync(0xffffffffu, ur23, 1);
            uz23 = __shfl_xor_sync(0xffffffffu, uz23, 1);
            float vr1 = ((qe & 1) ? pr3 : pr2) + ur23;
            float vz1 = ((qe & 1) ? pz3 : pz2) + uz23;
            float wr = (qe & 2) ? vr0 : vr1;
            float wz = (qe & 2) ? vz0 : vz1;
            wr = __shfl_xor_sync(0xffffffffu, wr, 2);
            wz = __shfl_xor_sync(0xffffffffu, wz, 2);
            float tot_r = ((qe & 2) ? vr1 : vr0) + wr;
            float tot_z = ((qe & 2) ? vz1 : vz0) + wz;

            // rh value on e<4 lanes; z to SMEM on e>=4 lanes (z STS issues before
            // the rh STG/RED below in warp program order -> covered by flag RTT)
            float rh = 0.f;
            if (e < 4) {
                float gate = __fdividef(1.f, 1.f + __expf(-(tot_r + gv)));
                float hold = hbuf[j * RB + qe * 36 + dd];
                rh = gate * hold;
            } else {
                float gate = __fdividef(1.f, 1.f + __expf(-(tot_z + gv)));
                zbuf[dd * 4 + qe] = gate;
            }
            // gather batch (lane&3)'s float4 of dims 4w..4w+3; lanes 0-3 store + RED
            {
                const int lane = t & 31;
                const int wa = t >> 5;
                const int b = lane & 3;
                float g0 = __shfl_sync(0xffffffffu, rh, b);
                float g1 = __shfl_sync(0xffffffffu, rh, 8 + b);
                float g2 = __shfl_sync(0xffffffffu, rh, 16 + b);
                float g3 = __shfl_sync(0xffffffffu, rh, 24 + b);
                if (lane < 4) {
                    stg_cg4(grh + b * 256 + j * 32 + 4 * wa, g0, g1, g2, g3);
                    red_rel(flagRH);            // release: orders THIS thread's stg
                }
            }
        } else {
            // ---- wait rh(s): warp 8 polls; warps 9-11 park at the bar
            if ((t >> 5) == 8) {
                const unsigned tgt = 256u * (unsigned)(s + 1);
                while (ld_acq(flagRH) < tgt) { }
            }
            asm volatile("bar.sync 2, 128;" ::: "memory");
            // ---- stage rh global -> smem (each thread two float4)
            {
                const int u = t - 256;
                const int r8 = u >> 4, b = (u >> 2) & 3, q2 = u & 3;
                const float* src = grh + b * 256 + r8 * 32 + q2 * 8;
                float4 v0 = ldg_cg4(src);
                float4 v1 = ldg_cg4(src + 4);
                *(float4*)&rhbuf[r8 * RB + b * 36 + q2 * 8]     = v0;
                *(float4*)&rhbuf[r8 * RB + b * 36 + q2 * 8 + 4] = v1;
            }
            asm volatile("bar.sync 2, 128;" ::: "memory");

            ull a0 = 0ull, a1 = 0ull, a2 = 0ull, a3 = 0ull;
            const float* rp0 = rhbuf + (2 * qh) * RB;
            const float* rp1 = rhbuf + (2 * qh + 1) * RB;
#define SUBB_BATCH(ACC, BIDX)                                                   \
            {                                                                   \
                const u2* pa = (const u2*)(rp0 + (BIDX) * 36);                  \
                const u2* pb = (const u2*)(rp1 + (BIDX) * 36);                  \
                _Pragma("unroll")                                               \
                for (int i = 0; i < 8; i++) {                                   \
                    u2 xa = pa[i];                                              \
                    FMA2(ACC, w[2 * i], xa.x); FMA2(ACC, w[2 * i + 1], xa.y);   \
                }                                                               \
                _Pragma("unroll")                                               \
                for (int i = 0; i < 8; i++) {                                   \
                    u2 xb = pb[i];                                              \
                    FMA2(ACC, w[16 + 2 * i], xb.x); FMA2(ACC, w[17 + 2 * i], xb.y); \
                }                                                               \
            }
            SUBB_BATCH(a0, 0)
            SUBB_BATCH(a1, 1)
            SUBB_BATCH(a2, 2)
            SUBB_BATCH(a3, 3)
#undef SUBB_BATCH

            float lo, hi, p0f, p1f, p2f, p3f;
            UNPK2(lo, hi, a0); p0f = lo + hi;
            UNPK2(lo, hi, a1); p1f = lo + hi;
            UNPK2(lo, hi, a2); p2f = lo + hi;
            UNPK2(lo, hi, a3); p3f = lo + hi;
            float u01 = (qh & 1) ? p0f : p1f;
            u01 = __shfl_xor_sync(0xffffffffu, u01, 1);
            float v0 = ((qh & 1) ? p1f : p0f) + u01;
            float u23 = (qh & 1) ? p2f : p3f;
            u23 = __shfl_xor_sync(0xffffffffu, u23, 1);
            float v1 = ((qh & 1) ? p3f : p2f) + u23;
            float uu = (qh & 2) ? v0 : v1;
            uu = __shfl_xor_sync(0xffffffffu, uu, 2);
            float tot = ((qh & 2) ? v1 : v0) + uu;

            float pre2 = tot + gv;
            float e2 = __expf(2.f * pre2);
            float htil = 1.f - __fdividef(2.f, e2 + 1.f);
            float hold = hbuf[j * RB + qh * 36 + dd];     // staged a full leg ago
            float z = zbuf[dd * 4 + qh];                  // volatile SMEM read
            float hn = fmaf(z, htil - hold, hold);

            // gather float4s of hn; lanes 0-7 store + RED
            {
                const int lane = t & 31;
                const int wb = (t >> 5) - 8;
                const int b = lane & 3;
                const int half = (lane >> 2) & 1;
                const int base = half ? 16 : 0;
                float g0 = __shfl_sync(0xffffffffu, hn, base + b + 0);
                float g1 = __shfl_sync(0xffffffffu, hn, base + b + 4);
                float g2 = __shfl_sync(0xffffffffu, hn, base + b + 8);
                float g3 = __shfl_sync(0xffffffffu, hn, base + b + 12);
                if (lane < 8) {
                    stg_cg4(ghg + b * 256 + j * 32 + 8 * wb + 4 * half, g0, g1, g2, g3);
                    red_rel(flagH);
                }
            }
            hs[((size_t)(cl * 4 + qh) * S + s) * H + dimg] = hn;
            if (s == S - 1) hlast[(size_t)(cl * 4 + qh) * H + dimg] = hn;
        }
    }
}

// ---------------- launch ------------------------------------------------------
extern "C" void kernel_launch(void* const* d_in, const int* in_sizes, int n_in,
                              void* d_out, int out_size)
{
    const float* x    = (const float*)d_in[0];
    const float* W_r  = (const float*)d_in[1];
    const float* b_r  = (const float*)d_in[2];
    const float* W_z  = (const float*)d_in[3];
    const float* b_z  = (const float*)d_in[4];
    const float* W_h  = (const float*)d_in[5];
    const float* b_h  = (const float*)d_in[6];
    const float* W_fc = (const float*)d_in[7];
    const float* b_fc = (const float*)d_in[8];
    float* out = (float*)d_out;
    float* hlast = out + (size_t)B * S * O;

    float *gx, *hsp, *Wx, *bx;
    cudaGetSymbolAddress((void**)&gx,  g_gx);
    cudaGetSymbolAddress((void**)&hsp, g_hs);
    cudaGetSymbolAddress((void**)&Wx,  g_Wx);
    cudaGetSymbolAddress((void**)&bx,  g_bx);

    pack_weights<<<G3, 64>>>(W_r, W_z, W_h, b_r, b_z, b_h);   // also resets exchange state
    gemm_bias<<<dim3(NROWS / 128, G3 / 64), 256>>>(x, Wx, bx, gx, G3);
    dummy_k<<<1, 32>>>();   // keeps gru_rec on the ncu capture slot
    gru_rec<<<128, 384>>>(gx, W_r, W_z, W_h, hsp, hlast);
    gemm_bias<<<dim3(NROWS / 128, O / 64), 256>>>(hsp, W_fc, b_fc, out, O);
}